// round 3
// baseline (speedup 1.0000x reference)
#include <cuda_runtime.h>
#include <math.h>

#define Bsz 256
#define Ssz 50
#define Csz 40
#define Dsz 256
#define TDIFF 1000

// ---------------- scratch (device globals: allocation-free) ----------------
__device__ float g_x[Bsz*Ssz*Dsz];          // embedding sums (B,S,D)
__device__ float g_Gih[Bsz*Ssz*4*Dsz];      // x@Wih^T + bih  (B,S,4D)
__device__ float g_h[Bsz*Dsz];
__device__ float g_c[Bsz*Dsz];
__device__ float g_G[Bsz*4*Dsz];            // per-step gate preactivations
__device__ float g_rnn[Bsz*Ssz*Dsz];        // LSTM hidden states
__device__ float g_w[Bsz*Ssz*Dsz];          // rnn@Whk^T + bhk
__device__ float g_featE[Bsz*64];           // e_k part of attention features (+b1)
__device__ float g_featW[Bsz*Ssz*64];       // w part of attention features
__device__ float g_aligned[Bsz*Ssz*Dsz];    // aligned_e_t
__device__ float g_pre[Bsz*Ssz*Dsz];        // noisy + temb
__device__ float g_alpha[Bsz];              // cumprod(1-beta)[t_b]
__device__ float g_WdiffT[Dsz*Dsz];         // Wdiff transposed (N,K) layout
__device__ float g_xmax[Bsz*Dsz];
__device__ float g_gmax[Bsz*Dsz];

// ---------------- generic NT GEMM: C[M,N] = A[M,K]·B[N,K]^T + bias + add ----
// Tiles: 64x64x16, 256 threads, 4x4 per-thread microtile. All dims are exact
// multiples of the tiles for every call site (M in {256,12800}, N in {64,256,1024}, K=256).
__global__ void gemm_nt(int M, int N, int K,
                        const float* __restrict__ A, int lda,
                        const float* __restrict__ B, int ldb,
                        const float* __restrict__ bias,
                        const float* __restrict__ add, int addStride,
                        float* __restrict__ C, int ldc)
{
    __shared__ float As[16][68];
    __shared__ float Bs[16][68];
    const int tid = threadIdx.x;
    const int m0 = blockIdx.y * 64;
    const int n0 = blockIdx.x * 64;
    const int tx = tid & 15;     // n group
    const int ty = tid >> 4;     // m group
    const int lr = tid >> 2;     // 0..63 tile row for loads
    const int lc = (tid & 3) * 4;

    float acc[4][4] = {};

    for (int k0 = 0; k0 < K; k0 += 16) {
        float4 a4 = *(const float4*)(A + (size_t)(m0 + lr) * lda + k0 + lc);
        float4 b4 = *(const float4*)(B + (size_t)(n0 + lr) * ldb + k0 + lc);
        As[lc+0][lr] = a4.x; As[lc+1][lr] = a4.y; As[lc+2][lr] = a4.z; As[lc+3][lr] = a4.w;
        Bs[lc+0][lr] = b4.x; Bs[lc+1][lr] = b4.y; Bs[lc+2][lr] = b4.z; Bs[lc+3][lr] = b4.w;
        __syncthreads();
        #pragma unroll
        for (int k = 0; k < 16; k++) {
            float a[4], b[4];
            #pragma unroll
            for (int i = 0; i < 4; i++) a[i] = As[k][ty*4 + i];
            #pragma unroll
            for (int j = 0; j < 4; j++) b[j] = Bs[k][tx*4 + j];
            #pragma unroll
            for (int i = 0; i < 4; i++)
                #pragma unroll
                for (int j = 0; j < 4; j++)
                    acc[i][j] = fmaf(a[i], b[j], acc[i][j]);
        }
        __syncthreads();
    }

    #pragma unroll
    for (int i = 0; i < 4; i++) {
        int row = m0 + ty*4 + i;
        #pragma unroll
        for (int j = 0; j < 4; j++) {
            int col = n0 + tx*4 + j;
            float v = acc[i][j];
            if (bias) v += bias[col];
            if (add)  v += add[(size_t)row * addStride + col];
            C[(size_t)row * ldc + col] = v;
        }
    }
}

// ---------------- embedding gather-sum ----------------
__global__ void embed_kernel(const int* __restrict__ seqs,
                             const float* __restrict__ emb)
{
    int bs = blockIdx.x;          // b*S + s
    int d  = threadIdx.x;         // 0..255
    __shared__ int idx[Csz];
    if (threadIdx.x < Csz) idx[threadIdx.x] = seqs[bs * Csz + threadIdx.x];
    __syncthreads();
    float acc = 0.f;
    #pragma unroll 8
    for (int c = 0; c < Csz; c++)
        acc += __ldg(emb + (size_t)idx[c] * Dsz + d);
    g_x[(size_t)bs * Dsz + d] = acc;
}

// ---------------- diffusion alpha lookup ----------------
__global__ void alpha_kernel(const int* __restrict__ t)
{
    __shared__ float tab[TDIFF];
    if (threadIdx.x == 0) {
        float a = 1.f;
        for (int i = 0; i < TDIFF; i++) {
            float beta = 1e-4f + (0.02f - 1e-4f) * (float)i / (float)(TDIFF - 1);
            a *= (1.f - beta);
            tab[i] = a;
        }
    }
    __syncthreads();
    if (threadIdx.x < Bsz) g_alpha[threadIdx.x] = tab[t[threadIdx.x]];
}

// ---------------- LSTM gate nonlinearity + state update ----------------
__device__ __forceinline__ float sigf(float x) { return 1.f / (1.f + expf(-x)); }

__global__ void lstm_gates(int t)
{
    int b = blockIdx.x, d = threadIdx.x;
    const float* g = g_G + (size_t)b * 4 * Dsz;
    float i_ = sigf(g[d]);
    float f_ = sigf(g[d + Dsz]);
    float gg = tanhf(g[d + 2*Dsz]);
    float o_ = sigf(g[d + 3*Dsz]);
    size_t hi = (size_t)b * Dsz + d;
    float c = f_ * g_c[hi] + i_ * gg;
    float h = o_ * tanhf(c);
    g_c[hi] = c;
    g_h[hi] = h;
    g_rnn[((size_t)b * Ssz + t) * Dsz + d] = h;
}

// ---------------- attention + aligned_e_t ----------------
__global__ void attn_kernel(const float* __restrict__ W2,
                            const float* __restrict__ b2)
{
    int s = blockIdx.x;           // 0..S-1
    int b = blockIdx.y;
    int tid = threadIdx.x;        // 256
    const float* ek = g_x + (size_t)b * Ssz * Dsz;   // x[b,0,:]
    size_t orow = ((size_t)b * Ssz + s) * Dsz;
    if (s == 0) { g_aligned[orow + tid] = ek[tid]; return; }

    __shared__ float s0[64], s1[64];
    __shared__ float a0s, a1s;
    int sm1 = s - 1;
    if (tid < 64) {
        float f = tanhf(g_featE[b*64 + tid] + g_featW[((size_t)b*Ssz + sm1)*64 + tid]);
        s0[tid] = f * W2[tid];
        s1[tid] = f * W2[64 + tid];
    }
    __syncthreads();
    if (tid == 0) {
        float l0 = b2[0], l1 = b2[1];
        for (int j = 0; j < 64; j++) { l0 += s0[j]; l1 += s1[j]; }
        float m = fmaxf(l0, l1);
        float e0 = expf(l0 - m), e1 = expf(l1 - m);
        float inv = 1.f / (e0 + e1);
        a0s = e0 * inv; a1s = e1 * inv;
    }
    __syncthreads();
    float wv = g_w[((size_t)b * Ssz + sm1) * Dsz + tid];
    g_aligned[orow + tid] = a0s * ek[tid] + a1s * wv;
}

// ---------------- diffusion: noisy + temb ----------------
__global__ void diff_prep(const float* __restrict__ noise,
                          const float* __restrict__ temb,
                          const int* __restrict__ t)
{
    int bs = blockIdx.x;
    int b = bs / Ssz;
    int d = threadIdx.x;
    float al = g_alpha[b];
    float sa = sqrtf(al), sn = sqrtf(1.f - al);
    size_t i = (size_t)bs * Dsz + d;
    g_pre[i] = g_aligned[i] * sa + noise[i] * sn + temb[(size_t)t[b] * Dsz + d];
}

__global__ void transpose_wdiff(const float* __restrict__ Wdiff)
{
    int n = blockIdx.x, k = threadIdx.x;
    g_WdiffT[n * Dsz + k] = __ldg(Wdiff + k * Dsz + n);
}

// ---------------- pooling (max over S) ----------------
__global__ void pool_kernel(const float* __restrict__ noise,
                            const float* __restrict__ pn)
{
    int b = blockIdx.x, d = threadIdx.x;
    float xm = -INFINITY, gm = -INFINITY;
    for (int s = 0; s < Ssz; s++) {
        size_t i = ((size_t)b * Ssz + s) * Dsz + d;
        xm = fmaxf(xm, g_x[i]);
        float gv = g_aligned[i] + noise[i] - pn[i];
        gm = fmaxf(gm, gv);
    }
    g_xmax[(size_t)b * Dsz + d] = xm;
    g_gmax[(size_t)b * Dsz + d] = gm;
}

// ---------------- final projections ----------------
__global__ void final_kernel(const float* __restrict__ Wout,
                             const float* __restrict__ bout,
                             float* __restrict__ out)
{
    int b = blockIdx.x, d = threadIdx.x;
    __shared__ float4 red[256];
    float xv = g_xmax[(size_t)b * Dsz + d];
    float gv = g_gmax[(size_t)b * Dsz + d];
    red[d] = make_float4(xv * Wout[d], xv * Wout[Dsz + d],
                         gv * Wout[d], gv * Wout[Dsz + d]);
    __syncthreads();
    for (int off = 128; off > 0; off >>= 1) {
        if (d < off) {
            float4 a = red[d], c = red[d + off];
            red[d] = make_float4(a.x + c.x, a.y + c.y, a.z + c.z, a.w + c.w);
        }
        __syncthreads();
    }
    if (d == 0) {
        float4 r = red[0];
        out[b*2 + 0]              = r.x + bout[0];
        out[b*2 + 1]              = r.y + bout[1];
        out[2*Bsz + b*2 + 0]      = r.z + bout[0];
        out[2*Bsz + b*2 + 1]      = r.w + bout[1];
    }
}

// ---------------- host ----------------
static float* sym(const void* s)
{
    void* p = nullptr;
    cudaGetSymbolAddress(&p, s);
    return (float*)p;
}

extern "C" void kernel_launch(void* const* d_in, const int* in_sizes, int n_in,
                              void* d_out, int out_size)
{
    const int*   seqs   = (const int*)  d_in[0];
    const int*   tdiff  = (const int*)  d_in[5];
    const float* noise  = (const float*)d_in[6];
    const float* emb    = (const float*)d_in[7];
    const float* Wih    = (const float*)d_in[8];
    const float* Whh    = (const float*)d_in[9];
    const float* bih    = (const float*)d_in[10];
    const float* bhh    = (const float*)d_in[11];
    const float* Whk    = (const float*)d_in[12];
    const float* bhk    = (const float*)d_in[13];
    const float* W1     = (const float*)d_in[14];
    const float* b1     = (const float*)d_in[15];
    const float* W2     = (const float*)d_in[16];
    const float* b2     = (const float*)d_in[17];
    const float* Wdiff  = (const float*)d_in[18];
    const float* bdiff  = (const float*)d_in[19];
    const float* temb   = (const float*)d_in[20];
    const float* Wout   = (const float*)d_in[21];
    const float* bout   = (const float*)d_in[22];
    float* out = (float*)d_out;

    float* p_x    = sym(g_x);
    float* p_Gih  = sym(g_Gih);
    float* p_h    = sym(g_h);
    float* p_c    = sym(g_c);
    float* p_G    = sym(g_G);
    float* p_rnn  = sym(g_rnn);
    float* p_w    = sym(g_w);
    float* p_fE   = sym(g_featE);
    float* p_fW   = sym(g_featW);
    float* p_pre  = sym(g_pre);
    float* p_WdT  = sym(g_WdiffT);

    const int MD = 4 * Dsz;            // 1024
    float* pn_out = out + 4 * Bsz;     // predicted_noise region (after pool_x, gen_pool_x)
    float* nn_out = out + 4 * Bsz + (size_t)Bsz * Ssz * Dsz;

    // 1) alpha lookup table
    alpha_kernel<<<1, 256>>>(tdiff);

    // 2) embedding gather-sum -> g_x
    embed_kernel<<<Bsz * Ssz, Dsz>>>(seqs, emb);

    // 3) Gih = x @ Wih^T + bih   (M=12800, N=1024, K=256)
    gemm_nt<<<dim3(MD/64, (Bsz*Ssz)/64), 256>>>(Bsz*Ssz, MD, Dsz,
        p_x, Dsz, Wih, Dsz, bih, nullptr, 0, p_Gih, MD);

    // 4) LSTM: 50 sequential steps
    cudaMemsetAsync(p_h, 0, Bsz * Dsz * sizeof(float));
    cudaMemsetAsync(p_c, 0, Bsz * Dsz * sizeof(float));
    for (int t = 0; t < Ssz; t++) {
        // G = h @ Whh^T + bhh + Gih[:,t,:]  (M=256, N=1024, K=256)
        gemm_nt<<<dim3(MD/64, Bsz/64), 256>>>(Bsz, MD, Dsz,
            p_h, Dsz, Whh, Dsz, bhh, p_Gih + (size_t)t * MD, Ssz * MD, p_G, MD);
        lstm_gates<<<Bsz, Dsz>>>(t);
    }

    // 5) w = rnn @ Whk^T + bhk   (M=12800, N=256, K=256)
    gemm_nt<<<dim3(Dsz/64, (Bsz*Ssz)/64), 256>>>(Bsz*Ssz, Dsz, Dsz,
        p_rnn, Dsz, Whk, Dsz, bhk, nullptr, 0, p_w, Dsz);

    // 6) attention features
    // featE = e_k @ W1[:, :256]^T + b1   (rows of x with lda = S*D)
    gemm_nt<<<dim3(1, Bsz/64), 256>>>(Bsz, 64, Dsz,
        p_x, Ssz * Dsz, W1, 2 * Dsz, b1, nullptr, 0, p_fE, 64);
    // featW = w @ W1[:, 256:]^T          (all S rows; last is unused)
    gemm_nt<<<dim3(1, (Bsz*Ssz)/64), 256>>>(Bsz*Ssz, 64, Dsz,
        p_w, Dsz, W1 + Dsz, 2 * Dsz, nullptr, nullptr, 0, p_fW, 64);

    // 7) attention softmax + aligned_e_t
    attn_kernel<<<dim3(Ssz, Bsz), Dsz>>>(W2, b2);

    // 8) diffusion prep: pre = aligned*sqrt(a) + noise*sqrt(1-a) + temb[t]
    diff_prep<<<Bsz * Ssz, Dsz>>>(noise, temb, tdiff);

    // 9) predicted_noise = pre @ Wdiff + bdiff  (Wdiff used untransposed -> pre-transpose)
    transpose_wdiff<<<Dsz, Dsz>>>(Wdiff);
    gemm_nt<<<dim3(Dsz/64, (Bsz*Ssz)/64), 256>>>(Bsz*Ssz, Dsz, Dsz,
        p_pre, Dsz, p_WdT, Dsz, bdiff, nullptr, 0, pn_out, Dsz);

    // 10) max-pool over S for x and gen_x
    pool_kernel<<<Bsz, Dsz>>>(noise, pn_out);

    // 11) pool_x / gen_pool_x projections
    final_kernel<<<Bsz, Dsz>>>(Wout, bout, out);

    // 12) normal_noise passthrough
    cudaMemcpyAsync(nn_out, noise, (size_t)Bsz * Ssz * Dsz * sizeof(float),
                    cudaMemcpyDeviceToDevice);
}

// round 4
// speedup vs baseline: 1.4239x; 1.4239x over previous
#include <cuda_runtime.h>
#include <math.h>

#define Bsz 256
#define Ssz 50
#define Csz 40
#define Dsz 256
#define TDIFF 1000

#define LSTM_GX 16   // n-blocks: 16 h-dims each
#define LSTM_GY 8    // m-blocks: 32 batch rows each
#define LSTM_NBLK (LSTM_GX*LSTM_GY)

// ---------------- scratch (device globals: allocation-free) ----------------
__device__ float g_x[Bsz*Ssz*Dsz];          // embedding sums (B,S,D)
__device__ float g_Gih[Bsz*Ssz*4*Dsz];      // x@Wih^T + bih + bhh  (B,S,4D)
__device__ float g_hbuf[2][Bsz*Dsz];        // LSTM h double buffer
__device__ float g_rnn[Bsz*Ssz*Dsz];        // LSTM hidden states
__device__ float g_w[Bsz*Ssz*Dsz];          // rnn@Whk^T + bhk
__device__ float g_featE[Bsz*64];           // e_k part of attention features (+b1)
__device__ float g_featW[Bsz*Ssz*64];       // w part of attention features
__device__ float g_aligned[Bsz*Ssz*Dsz];    // aligned_e_t
__device__ float g_pre[Bsz*Ssz*Dsz];        // noisy + temb
__device__ float g_alpha[Bsz];              // cumprod(1-beta)[t_b]
__device__ float g_WdiffT[Dsz*Dsz];         // Wdiff transposed (N,K) layout
__device__ float g_xmax[Bsz*Dsz];
__device__ float g_gmax[Bsz*Dsz];
__device__ float g_bsum[4*Dsz];             // bih + bhh

// software grid barrier state
__device__ unsigned g_barCnt;
__device__ volatile unsigned g_barGen;

// ---------------- generic NT GEMM: C[M,N] = A[M,K]·B[N,K]^T + bias + add ----
__global__ void gemm_nt(int M, int N, int K,
                        const float* __restrict__ A, int lda,
                        const float* __restrict__ B, int ldb,
                        const float* __restrict__ bias,
                        const float* __restrict__ add, int addStride,
                        float* __restrict__ C, int ldc)
{
    __shared__ float As[16][68];
    __shared__ float Bs[16][68];
    const int tid = threadIdx.x;
    const int m0 = blockIdx.y * 64;
    const int n0 = blockIdx.x * 64;
    const int tx = tid & 15;     // n group
    const int ty = tid >> 4;     // m group
    const int lr = tid >> 2;     // 0..63 tile row for loads
    const int lc = (tid & 3) * 4;

    float acc[4][4] = {};

    for (int k0 = 0; k0 < K; k0 += 16) {
        float4 a4 = *(const float4*)(A + (size_t)(m0 + lr) * lda + k0 + lc);
        float4 b4 = *(const float4*)(B + (size_t)(n0 + lr) * ldb + k0 + lc);
        As[lc+0][lr] = a4.x; As[lc+1][lr] = a4.y; As[lc+2][lr] = a4.z; As[lc+3][lr] = a4.w;
        Bs[lc+0][lr] = b4.x; Bs[lc+1][lr] = b4.y; Bs[lc+2][lr] = b4.z; Bs[lc+3][lr] = b4.w;
        __syncthreads();
        #pragma unroll
        for (int k = 0; k < 16; k++) {
            float a[4], b[4];
            #pragma unroll
            for (int i = 0; i < 4; i++) a[i] = As[k][ty*4 + i];
            #pragma unroll
            for (int j = 0; j < 4; j++) b[j] = Bs[k][tx*4 + j];
            #pragma unroll
            for (int i = 0; i < 4; i++)
                #pragma unroll
                for (int j = 0; j < 4; j++)
                    acc[i][j] = fmaf(a[i], b[j], acc[i][j]);
        }
        __syncthreads();
    }

    #pragma unroll
    for (int i = 0; i < 4; i++) {
        int row = m0 + ty*4 + i;
        #pragma unroll
        for (int j = 0; j < 4; j++) {
            int col = n0 + tx*4 + j;
            float v = acc[i][j];
            if (bias) v += bias[col];
            if (add)  v += add[(size_t)row * addStride + col];
            C[(size_t)row * ldc + col] = v;
        }
    }
}

// ---------------- embedding gather-sum ----------------
__global__ void embed_kernel(const int* __restrict__ seqs,
                             const float* __restrict__ emb)
{
    int bs = blockIdx.x;          // b*S + s
    int d  = threadIdx.x;         // 0..255
    __shared__ int idx[Csz];
    if (threadIdx.x < Csz) idx[threadIdx.x] = seqs[bs * Csz + threadIdx.x];
    __syncthreads();
    float acc = 0.f;
    #pragma unroll 8
    for (int c = 0; c < Csz; c++)
        acc += __ldg(emb + (size_t)idx[c] * Dsz + d);
    g_x[(size_t)bs * Dsz + d] = acc;
}

// ---------------- diffusion alpha lookup ----------------
__global__ void alpha_kernel(const int* __restrict__ t)
{
    __shared__ float tab[TDIFF];
    if (threadIdx.x == 0) {
        float a = 1.f;
        for (int i = 0; i < TDIFF; i++) {
            float beta = 1e-4f + (0.02f - 1e-4f) * (float)i / (float)(TDIFF - 1);
            a *= (1.f - beta);
            tab[i] = a;
        }
    }
    __syncthreads();
    if (threadIdx.x < Bsz) g_alpha[threadIdx.x] = tab[t[threadIdx.x]];
}

// ---------------- bias sum ----------------
__global__ void bsum_kernel(const float* __restrict__ bih,
                            const float* __restrict__ bhh)
{
    int i = blockIdx.x * 256 + threadIdx.x;
    g_bsum[i] = bih[i] + bhh[i];
}

// ---------------- fused persistent LSTM ----------------
__device__ __forceinline__ float sigf(float x) { return 1.f / (1.f + expf(-x)); }

__device__ __forceinline__ void gridBarrier()
{
    __syncthreads();
    if (threadIdx.x == 0) {
        __threadfence();                       // publish this block's writes
        unsigned gen = g_barGen;
        __threadfence();                       // order gen read before arrive
        if (atomicAdd(&g_barCnt, 1u) == LSTM_NBLK - 1) {
            g_barCnt = 0;
            __threadfence();
            g_barGen = gen + 1;
        } else {
            while (g_barGen == gen) __nanosleep(64);
        }
        __threadfence();                       // acquire
    }
    __syncthreads();
}

// Shared layout: Bs[256][68] (permuted Whh slice, persistent) + As[256][36]
#define LSTM_SMEM ((256*68 + 256*36) * (int)sizeof(float))

__global__ void __launch_bounds__(128, 1)
lstm_fused(const float* __restrict__ Whh)
{
    extern __shared__ float sh[];
    float* Bs = sh;               // [k][r], r = j*4+g  (stride 68)
    float* As = sh + 256*68;      // [k][m]             (stride 36)

    const int tid = threadIdx.x;
    const int nb  = blockIdx.x;   // 0..15 : h-dims nb*16..+15
    const int mb  = blockIdx.y;   // 0..7  : batch rows mb*32..+31
    const int m0  = mb * 32;
    const int tx  = tid & 15;     // h-dim within block
    const int ty  = tid >> 4;     // m group of 4
    const int d   = nb * 16 + tx;

    // one-time: load Whh gate-interleaved slice into persistent shared
    {
        int r = tid >> 1;                 // 0..63
        int g = r & 3, j = r >> 2;
        const float* src = Whh + (size_t)(g * 256 + nb * 16 + j) * 256;
        for (int q = (tid & 1); q < 64; q += 2) {
            float4 v = *(const float4*)(src + q * 4);
            Bs[(q*4+0)*68 + r] = v.x;
            Bs[(q*4+1)*68 + r] = v.y;
            Bs[(q*4+2)*68 + r] = v.z;
            Bs[(q*4+3)*68 + r] = v.w;
        }
    }
    float c[4] = {0.f, 0.f, 0.f, 0.f};
    __syncthreads();

    for (int t = 0; t < Ssz; t++) {
        float acc[4][4] = {};
        if (t > 0) {
            // stage h tile (32 x 256) into shared, transposed
            const float* hsrc = g_hbuf[(t + 1) & 1] + (size_t)m0 * Dsz;
            int rr = tid >> 2;            // 0..31
            const float* arow = hsrc + (size_t)rr * Dsz;
            for (int q = (tid & 3); q < 64; q += 4) {
                float4 v = *(const float4*)(arow + q * 4);
                As[(q*4+0)*36 + rr] = v.x;
                As[(q*4+1)*36 + rr] = v.y;
                As[(q*4+2)*36 + rr] = v.z;
                As[(q*4+3)*36 + rr] = v.w;
            }
            __syncthreads();
            #pragma unroll 8
            for (int k = 0; k < 256; k++) {
                float4 a = *(const float4*)(As + k * 36 + ty * 4);
                float4 b = *(const float4*)(Bs + k * 68 + tx * 4);
                float av[4] = {a.x, a.y, a.z, a.w};
                float bv[4] = {b.x, b.y, b.z, b.w};
                #pragma unroll
                for (int i = 0; i < 4; i++)
                    #pragma unroll
                    for (int j = 0; j < 4; j++)
                        acc[i][j] = fmaf(av[i], bv[j], acc[i][j]);
            }
        }
        // epilogue: add Gih, gates, update c/h (c stays in registers)
        float* hdst = g_hbuf[t & 1];
        #pragma unroll
        for (int i = 0; i < 4; i++) {
            int b = m0 + ty * 4 + i;
            size_t gbase = ((size_t)b * Ssz + t) * (4 * Dsz) + d;
            float gi = acc[i][0] + g_Gih[gbase];
            float gf = acc[i][1] + g_Gih[gbase + 256];
            float gg = acc[i][2] + g_Gih[gbase + 512];
            float go = acc[i][3] + g_Gih[gbase + 768];
            float iv = sigf(gi), fv = sigf(gf);
            float gv = tanhf(gg), ov = sigf(go);
            c[i] = fv * c[i] + iv * gv;
            float h = ov * tanhf(c[i]);
            hdst[(size_t)b * Dsz + d] = h;
            g_rnn[((size_t)b * Ssz + t) * Dsz + d] = h;
        }
        gridBarrier();
    }
}

// ---------------- attention + aligned_e_t ----------------
__global__ void attn_kernel(const float* __restrict__ W2,
                            const float* __restrict__ b2)
{
    int s = blockIdx.x;
    int b = blockIdx.y;
    int tid = threadIdx.x;
    const float* ek = g_x + (size_t)b * Ssz * Dsz;   // x[b,0,:]
    size_t orow = ((size_t)b * Ssz + s) * Dsz;
    if (s == 0) { g_aligned[orow + tid] = ek[tid]; return; }

    __shared__ float s0[64], s1[64];
    __shared__ float a0s, a1s;
    int sm1 = s - 1;
    if (tid < 64) {
        float f = tanhf(g_featE[b*64 + tid] + g_featW[((size_t)b*Ssz + sm1)*64 + tid]);
        s0[tid] = f * W2[tid];
        s1[tid] = f * W2[64 + tid];
    }
    __syncthreads();
    if (tid == 0) {
        float l0 = b2[0], l1 = b2[1];
        for (int j = 0; j < 64; j++) { l0 += s0[j]; l1 += s1[j]; }
        float m = fmaxf(l0, l1);
        float e0 = expf(l0 - m), e1 = expf(l1 - m);
        float inv = 1.f / (e0 + e1);
        a0s = e0 * inv; a1s = e1 * inv;
    }
    __syncthreads();
    float wv = g_w[((size_t)b * Ssz + sm1) * Dsz + tid];
    g_aligned[orow + tid] = a0s * ek[tid] + a1s * wv;
}

// ---------------- diffusion: noisy + temb ----------------
__global__ void diff_prep(const float* __restrict__ noise,
                          const float* __restrict__ temb,
                          const int* __restrict__ t)
{
    int bs = blockIdx.x;
    int b = bs / Ssz;
    int d = threadIdx.x;
    float al = g_alpha[b];
    float sa = sqrtf(al), sn = sqrtf(1.f - al);
    size_t i = (size_t)bs * Dsz + d;
    g_pre[i] = g_aligned[i] * sa + noise[i] * sn + temb[(size_t)t[b] * Dsz + d];
}

__global__ void transpose_wdiff(const float* __restrict__ Wdiff)
{
    int n = blockIdx.x, k = threadIdx.x;
    g_WdiffT[n * Dsz + k] = __ldg(Wdiff + k * Dsz + n);
}

// ---------------- pooling (max over S) ----------------
__global__ void pool_kernel(const float* __restrict__ noise,
                            const float* __restrict__ pn)
{
    int b = blockIdx.x, d = threadIdx.x;
    float xm = -INFINITY, gm = -INFINITY;
    for (int s = 0; s < Ssz; s++) {
        size_t i = ((size_t)b * Ssz + s) * Dsz + d;
        xm = fmaxf(xm, g_x[i]);
        float gv = g_aligned[i] + noise[i] - pn[i];
        gm = fmaxf(gm, gv);
    }
    g_xmax[(size_t)b * Dsz + d] = xm;
    g_gmax[(size_t)b * Dsz + d] = gm;
}

// ---------------- final projections ----------------
__global__ void final_kernel(const float* __restrict__ Wout,
                             const float* __restrict__ bout,
                             float* __restrict__ out)
{
    int b = blockIdx.x, d = threadIdx.x;
    __shared__ float4 red[256];
    float xv = g_xmax[(size_t)b * Dsz + d];
    float gv = g_gmax[(size_t)b * Dsz + d];
    red[d] = make_float4(xv * Wout[d], xv * Wout[Dsz + d],
                         gv * Wout[d], gv * Wout[Dsz + d]);
    __syncthreads();
    for (int off = 128; off > 0; off >>= 1) {
        if (d < off) {
            float4 a = red[d], c = red[d + off];
            red[d] = make_float4(a.x + c.x, a.y + c.y, a.z + c.z, a.w + c.w);
        }
        __syncthreads();
    }
    if (d == 0) {
        float4 r = red[0];
        out[b*2 + 0]              = r.x + bout[0];
        out[b*2 + 1]              = r.y + bout[1];
        out[2*Bsz + b*2 + 0]      = r.z + bout[0];
        out[2*Bsz + b*2 + 1]      = r.w + bout[1];
    }
}

// ---------------- host ----------------
static float* sym(const void* s)
{
    void* p = nullptr;
    cudaGetSymbolAddress(&p, s);
    return (float*)p;
}

extern "C" void kernel_launch(void* const* d_in, const int* in_sizes, int n_in,
                              void* d_out, int out_size)
{
    const int*   seqs   = (const int*)  d_in[0];
    const int*   tdiff  = (const int*)  d_in[5];
    const float* noise  = (const float*)d_in[6];
    const float* emb    = (const float*)d_in[7];
    const float* Wih    = (const float*)d_in[8];
    const float* Whh    = (const float*)d_in[9];
    const float* bih    = (const float*)d_in[10];
    const float* bhh    = (const float*)d_in[11];
    const float* Whk    = (const float*)d_in[12];
    const float* bhk    = (const float*)d_in[13];
    const float* W1     = (const float*)d_in[14];
    const float* b1     = (const float*)d_in[15];
    const float* W2     = (const float*)d_in[16];
    const float* b2     = (const float*)d_in[17];
    const float* Wdiff  = (const float*)d_in[18];
    const float* bdiff  = (const float*)d_in[19];
    const float* temb   = (const float*)d_in[20];
    const float* Wout   = (const float*)d_in[21];
    const float* bout   = (const float*)d_in[22];
    float* out = (float*)d_out;

    float* p_x    = sym(g_x);
    float* p_Gih  = sym(g_Gih);
    float* p_rnn  = sym(g_rnn);
    float* p_w    = sym(g_w);
    float* p_fE   = sym(g_featE);
    float* p_fW   = sym(g_featW);
    float* p_pre  = sym(g_pre);
    float* p_WdT  = sym(g_WdiffT);
    float* p_bsum = sym(g_bsum);

    static bool attr_done = false;
    if (!attr_done) {
        cudaFuncSetAttribute(lstm_fused,
                             cudaFuncAttributeMaxDynamicSharedMemorySize,
                             LSTM_SMEM);
        attr_done = true;
    }

    const int MD = 4 * Dsz;            // 1024
    float* pn_out = out + 4 * Bsz;     // predicted_noise region
    float* nn_out = out + 4 * Bsz + (size_t)Bsz * Ssz * Dsz;

    // 1) alpha lookup + bias sum
    alpha_kernel<<<1, 256>>>(tdiff);
    bsum_kernel<<<4, 256>>>(bih, bhh);

    // 2) embedding gather-sum -> g_x
    embed_kernel<<<Bsz * Ssz, Dsz>>>(seqs, emb);

    // 3) Gih = x @ Wih^T + (bih+bhh)   (M=12800, N=1024, K=256)
    gemm_nt<<<dim3(MD/64, (Bsz*Ssz)/64), 256>>>(Bsz*Ssz, MD, Dsz,
        p_x, Dsz, Wih, Dsz, p_bsum, nullptr, 0, p_Gih, MD);

    // 4) fused persistent LSTM: all 50 steps in one launch
    lstm_fused<<<dim3(LSTM_GX, LSTM_GY), 128, LSTM_SMEM>>>(Whh);

    // 5) w = rnn @ Whk^T + bhk   (M=12800, N=256, K=256)
    gemm_nt<<<dim3(Dsz/64, (Bsz*Ssz)/64), 256>>>(Bsz*Ssz, Dsz, Dsz,
        p_rnn, Dsz, Whk, Dsz, bhk, nullptr, 0, p_w, Dsz);

    // 6) attention features
    gemm_nt<<<dim3(1, Bsz/64), 256>>>(Bsz, 64, Dsz,
        p_x, Ssz * Dsz, W1, 2 * Dsz, b1, nullptr, 0, p_fE, 64);
    gemm_nt<<<dim3(1, (Bsz*Ssz)/64), 256>>>(Bsz*Ssz, 64, Dsz,
        p_w, Dsz, W1 + Dsz, 2 * Dsz, nullptr, nullptr, 0, p_fW, 64);

    // 7) attention softmax + aligned_e_t
    attn_kernel<<<dim3(Ssz, Bsz), Dsz>>>(W2, b2);

    // 8) diffusion prep
    diff_prep<<<Bsz * Ssz, Dsz>>>(noise, temb, tdiff);

    // 9) predicted_noise = pre @ Wdiff + bdiff
    transpose_wdiff<<<Dsz, Dsz>>>(Wdiff);
    gemm_nt<<<dim3(Dsz/64, (Bsz*Ssz)/64), 256>>>(Bsz*Ssz, Dsz, Dsz,
        p_pre, Dsz, p_WdT, Dsz, bdiff, nullptr, 0, pn_out, Dsz);

    // 10) max-pool over S
    pool_kernel<<<Bsz, Dsz>>>(noise, pn_out);

    // 11) final projections
    final_kernel<<<Bsz, Dsz>>>(Wout, bout, out);

    // 12) normal_noise passthrough
    cudaMemcpyAsync(nn_out, noise, (size_t)Bsz * Ssz * Dsz * sizeof(float),
                    cudaMemcpyDeviceToDevice);
}